// round 15
// baseline (speedup 1.0000x reference)
#include <cuda_runtime.h>
#include <cuda_fp16.h>
#include <math.h>

#define BB   2
#define TT   1024
#define CC   1024
#define NHH  16
#define DHH  64
#define LLAYERS 4
#define HFF_ 2816
#define MM   (BB*TT)          // 2048 rows

// ---------------- scratch (static device globals) ---------------------------
__device__ __align__(16) float  g_h   [MM*CC];
__device__ __align__(16) __half g_a2  [MM*2*CC];     // rms acts [hi|lo]
__device__ __align__(16) float  g_qkv [MM*3*CC];     // fused q|k|v (fp32)
__device__ __align__(16) __half g_qh  [MM*CC];       // roped q hi (pre-scaled)
__device__ __align__(16) __half g_ql  [MM*CC];
__device__ __align__(16) __half g_kh  [MM*CC];
__device__ __align__(16) __half g_vth [MM*CC];       // V^T [b][h][d][t] hi
__device__ __align__(16) __half g_y2  [MM*2*CC];     // attn out [hi|lo]
__device__ __align__(16) float  g_u1  [MM*HFF_];
__device__ __align__(16) __half g_u12 [MM*2*HFF_];

// split fp16 weights, row layout [row][hi(K) | lo(K)]
__device__ __align__(16) __half g_wqkv2[LLAYERS*3*CC*2*CC];
__device__ __align__(16) __half g_wo2  [LLAYERS*CC*2*CC];
__device__ __align__(16) __half g_w12  [LLAYERS*HFF_*2*CC];
__device__ __align__(16) __half g_w22  [LLAYERS*HFF_*2*CC];
__device__ __align__(16) __half g_w32  [LLAYERS*CC*2*HFF_];

// ---------------- helpers ----------------------------------------------------
__device__ __forceinline__ void cp16(void* smem_dst, const void* gsrc) {
    unsigned d = (unsigned)__cvta_generic_to_shared(smem_dst);
    asm volatile("cp.async.ca.shared.global [%0], [%1], 16;\n" :: "r"(d), "l"(gsrc));
}
#define CP_COMMIT()  asm volatile("cp.async.commit_group;\n")
#define CP_WAIT(N)   asm volatile("cp.async.wait_group %0;\n" :: "n"(N))

__device__ __forceinline__ void mma16816(float* d, const unsigned* a, const unsigned* b) {
    asm volatile(
        "mma.sync.aligned.m16n8k16.row.col.f32.f16.f16.f32 "
        "{%0,%1,%2,%3}, {%4,%5,%6,%7}, {%8,%9}, {%0,%1,%2,%3};\n"
        : "+f"(d[0]), "+f"(d[1]), "+f"(d[2]), "+f"(d[3])
        : "r"(a[0]), "r"(a[1]), "r"(a[2]), "r"(a[3]), "r"(b[0]), "r"(b[1]));
}

__device__ __forceinline__ void ldsm4(unsigned addr, unsigned& r0, unsigned& r1,
                                      unsigned& r2, unsigned& r3) {
    asm volatile("ldmatrix.sync.aligned.m8n8.x4.shared.b16 {%0,%1,%2,%3}, [%4];\n"
                 : "=r"(r0), "=r"(r1), "=r"(r2), "=r"(r3) : "r"(addr));
}

__device__ __forceinline__ unsigned packh2(__half a, __half b) {
    return (unsigned)__half_as_ushort(a) | ((unsigned)__half_as_ushort(b) << 16);
}
__device__ __forceinline__ void pack2(float x, float y, unsigned& hi, unsigned& lo) {
    __half hx = __float2half(x), hy = __float2half(y);
    __half lx = __float2half(x - __half2float(hx));
    __half ly = __float2half(y - __half2float(hy));
    hi = packh2(hx, hy);
    lo = packh2(lx, ly);
}

// ---------------- weight split conversion (vectorized) -----------------------
__global__ void k_split_w4(const float* __restrict__ src, __half* __restrict__ dst,
                           int total4, int K) {
    int idx = blockIdx.x * blockDim.x + threadIdx.x;
    if (idx >= total4) return;
    int i4 = idx * 4;
    int r = i4 / K;
    int k = i4 - r * K;
    float4 v = *(const float4*)&src[i4];
    __half h0 = __float2half(v.x), h1 = __float2half(v.y);
    __half h2 = __float2half(v.z), h3 = __float2half(v.w);
    __half l0 = __float2half(v.x - __half2float(h0));
    __half l1 = __float2half(v.y - __half2float(h1));
    __half l2 = __float2half(v.z - __half2float(h2));
    __half l3 = __float2half(v.w - __half2float(h3));
    size_t off = (size_t)r*2*K + k;
    uint2 uh; uh.x = packh2(h0,h1); uh.y = packh2(h2,h3);
    uint2 ul; ul.x = packh2(l0,l1); ul.y = packh2(l2,l3);
    *(uint2*)&dst[off]     = uh;
    *(uint2*)&dst[off + K] = ul;
}

__global__ void k_split_qkv_w4(const float* __restrict__ wq,
                               const float* __restrict__ wkv,
                               __half* __restrict__ dst) {
    int idx = blockIdx.x * blockDim.x + threadIdx.x;
    if (idx >= LLAYERS*3*CC*CC/4) return;
    int i4  = idx * 4;
    int l   = i4 / (3*CC*CC);
    int rem = i4 - l*(3*CC*CC);
    int row = rem >> 10;
    int k   = rem & 1023;
    float4 v = (row < CC)
        ? *(const float4*)&wq [((size_t)l*CC   + row)      * CC + k]
        : *(const float4*)&wkv[((size_t)l*2*CC + (row-CC)) * CC + k];
    __half h0 = __float2half(v.x), h1 = __float2half(v.y);
    __half h2 = __float2half(v.z), h3 = __float2half(v.w);
    __half l0 = __float2half(v.x - __half2float(h0));
    __half l1 = __float2half(v.y - __half2float(h1));
    __half l2 = __float2half(v.z - __half2float(h2));
    __half l3 = __float2half(v.w - __half2float(h3));
    __half* d = dst + ((size_t)l*3*CC + row)*2*CC;
    uint2 uh; uh.x = packh2(h0,h1); uh.y = packh2(h2,h3);
    uint2 ul; ul.x = packh2(l0,l1); ul.y = packh2(l2,l3);
    *(uint2*)&d[k]      = uh;
    *(uint2*)&d[CC + k] = ul;
}

// ---------------- input projection: h = x @ w_in^T  (K=9) --------------------
__global__ void k_input_proj(const float* __restrict__ x,
                             const float* __restrict__ w,
                             float* __restrict__ h) {
    int idx = blockIdx.x * blockDim.x + threadIdx.x;
    if (idx >= MM*CC) return;
    int m = idx >> 10;
    int c = idx & 1023;
    const float* xr = x + m*9;
    const float* wr = w + c*9;
    float s = 0.f;
    #pragma unroll
    for (int f = 0; f < 9; ++f) s += xr[f] * wr[f];
    h[idx] = s;
}

// ---------------- RMSNorm -> split fp16 hi/lo (vectorized) -------------------
__global__ void k_rms_h(const float* __restrict__ in,
                        __half* __restrict__ out2,     // [M][2C]
                        const float* __restrict__ g) {
    int m = blockIdx.x;
    int c4 = threadIdx.x * 4;
    float4 v = *(const float4*)&in[(size_t)m*CC + c4];
    float s = v.x*v.x + v.y*v.y + v.z*v.z + v.w*v.w;
    __shared__ float red[256];
    red[threadIdx.x] = s;
    __syncthreads();
    #pragma unroll
    for (int off = 128; off > 0; off >>= 1) {
        if (threadIdx.x < off) red[threadIdx.x] += red[threadIdx.x + off];
        __syncthreads();
    }
    float inv = rsqrtf(red[0] * (1.0f/CC) + 1e-5f);
    float4 gv = *(const float4*)&g[c4];
    float o0 = v.x*inv*gv.x, o1 = v.y*inv*gv.y;
    float o2 = v.z*inv*gv.z, o3 = v.w*inv*gv.w;
    unsigned h01, l01, h23, l23;
    pack2(o0, o1, h01, l01);
    pack2(o2, o3, h23, l23);
    uint2 uh; uh.x = h01; uh.y = h23;
    uint2 ul; ul.x = l01; ul.y = l23;
    *(uint2*)&out2[(size_t)m*2*CC + c4]      = uh;
    *(uint2*)&out2[(size_t)m*2*CC + CC + c4] = ul;
}

// ---------------- 3-stage pipelined ldmatrix fp16x3 tensor-core GEMM ---------
// C[M,N] (+)= A[M,K]*W[N,K]^T as Ahi*Whi + Alo*Whi + Ahi*Wlo, single K pass.
// BM=BN=128, BK=32, 256 threads (8 warps, 4m x 2n, 32x64 warp tile).
// EPI: 0 = store fp32, 1 = add into fp32, 2 = silu(aux)*acc -> hi/lo fp16 out2.
#define GSTG 20480            // halves per stage (512 rows * 40)
#define GSMEM (3*GSTG*2)      // bytes = 122880
template<int EPI>
__global__ void __launch_bounds__(256, 1)
k_hgemm(const __half* __restrict__ A,
        const __half* __restrict__ W,
        float* __restrict__ C,
        const float* __restrict__ aux,
        __half* __restrict__ out2,
        int N, int K) {
    extern __shared__ __half sh[];
    int tid  = threadIdx.x;
    int wid  = tid >> 5, lane = tid & 31;
    int wm   = wid & 3,  wn   = wid >> 2;
    int g    = lane >> 2, t   = lane & 3;
    int m0   = blockIdx.y * 128, n0 = blockIdx.x * 128;
    int ld   = 2 * K;
    const int IT = K / 32;

    unsigned sb = (unsigned)__cvta_generic_to_shared(sh);
    unsigned aOff = (lane & 15)*80 + (lane >> 4)*16;
    unsigned bOff = ((lane & 7) + ((lane >> 4) << 3))*80 + ((lane >> 3) & 1)*16;

    float acc[2][8][4];
    #pragma unroll
    for (int mi = 0; mi < 2; ++mi)
        #pragma unroll
        for (int ni = 0; ni < 8; ++ni)
            #pragma unroll
            for (int q = 0; q < 4; ++q) acc[mi][ni][q] = 0.f;

    auto load_stage = [&](int st, int k0) {
        __half* base = sh + st*GSTG;
        #pragma unroll
        for (int i = 0; i < 8; ++i) {
            int c   = tid + i*256;
            int row = c >> 2;
            int kc  = (c & 3) * 8;
            const __half* src;
            if      (row < 128) src = A + (size_t)(m0 + row      )*ld + k0 + kc;
            else if (row < 256) src = A + (size_t)(m0 + row - 128)*ld + K + k0 + kc;
            else if (row < 384) src = W + (size_t)(n0 + row - 256)*ld + k0 + kc;
            else                src = W + (size_t)(n0 + row - 384)*ld + K + k0 + kc;
            cp16(base + row*40 + kc, src);
        }
    };

    auto compute_stage = [&](int st) {
        unsigned base = sb + st*(GSTG*2);
        unsigned aHb = base + (wm*32)*80 + aOff;
        unsigned aLb = aHb + 128*80;
        unsigned bHb = base + 256*80 + (wn*64)*80 + bOff;
        unsigned bLb = bHb + 128*80;
        #pragma unroll
        for (int kk = 0; kk < 32; kk += 16) {
            unsigned aH[2][4], aL[2][4], bh[8][2], bl[8][2];
            #pragma unroll
            for (int mi = 0; mi < 2; ++mi) {
                ldsm4(aHb + mi*16*80 + kk*2, aH[mi][0], aH[mi][1], aH[mi][2], aH[mi][3]);
                ldsm4(aLb + mi*16*80 + kk*2, aL[mi][0], aL[mi][1], aL[mi][2], aL[mi][3]);
            }
            #pragma unroll
            for (int nj = 0; nj < 4; ++nj) {
                ldsm4(bHb + nj*16*80 + kk*2,
                      bh[2*nj][0], bh[2*nj][1], bh[2*nj+1][0], bh[2*nj+1][1]);
                ldsm4(bLb + nj*16*80 + kk*2,
                      bl[2*nj][0], bl[2*nj][1], bl[2*nj+1][0], bl[2*nj+1][1]);
            }
            #pragma unroll
            for (int ni = 0; ni < 8; ++ni)
                #pragma unroll
                for (int mi = 0; mi < 2; ++mi) {
                    mma16816(acc[mi][ni], aH[mi], bh[ni]);
                    mma16816(acc[mi][ni], aL[mi], bh[ni]);
                    mma16816(acc[mi][ni], aH[mi], bl[ni]);
                }
        }
    };

    load_stage(0, 0);  CP_COMMIT();
    load_stage(1, 32); CP_COMMIT();
    for (int it = 0; it < IT; ++it) {
        CP_WAIT(1);
        __syncthreads();
        if (it + 2 < IT) load_stage((it+2)%3, (it+2)*32);
        CP_COMMIT();
        compute_stage(it % 3);
    }

    #pragma unroll
    for (int mi = 0; mi < 2; ++mi)
        #pragma unroll
        for (int ni = 0; ni < 8; ++ni) {
            int row = m0 + wm*32 + mi*16 + g;
            int col = n0 + wn*64 + ni*8 + 2*t;
            if (EPI == 0) {
                *(float2*)&C[(size_t)row*N + col] =
                    make_float2(acc[mi][ni][0], acc[mi][ni][1]);
                *(float2*)&C[(size_t)(row + 8)*N + col] =
                    make_float2(acc[mi][ni][2], acc[mi][ni][3]);
            } else if (EPI == 1) {
                float2* p0 = (float2*)&C[(size_t)row*N + col];
                float2* p1 = (float2*)&C[(size_t)(row + 8)*N + col];
                float2 v0 = *p0, v1 = *p1;
                v0.x += acc[mi][ni][0]; v0.y += acc[mi][ni][1];
                v1.x += acc[mi][ni][2]; v1.y += acc[mi][ni][3];
                *p0 = v0; *p1 = v1;
            } else {
                float2 a0v = *(const float2*)&aux[(size_t)row*N + col];
                float2 a1v = *(const float2*)&aux[(size_t)(row+8)*N + col];
                float v0 = a0v.x / (1.f + __expf(-a0v.x)) * acc[mi][ni][0];
                float v1 = a0v.y / (1.f + __expf(-a0v.y)) * acc[mi][ni][1];
                float v2 = a1v.x / (1.f + __expf(-a1v.x)) * acc[mi][ni][2];
                float v3 = a1v.y / (1.f + __expf(-a1v.y)) * acc[mi][ni][3];
                unsigned h01, l01, h23, l23;
                pack2(v0, v1, h01, l01);
                pack2(v2, v3, h23, l23);
                *(unsigned*)&out2[(size_t)row*2*N + col]          = h01;
                *(unsigned*)&out2[(size_t)row*2*N + N + col]      = l01;
                *(unsigned*)&out2[(size_t)(row+8)*2*N + col]      = h23;
                *(unsigned*)&out2[(size_t)(row+8)*2*N + N + col]  = l23;
            }
        }
}

// ---------------- RoPE + convert (tile-based, coalesced V^T, hi-only K/V) ----
// grid (TT/64, NH, B), 256 threads. Each CTA: 64 tokens x 64 dims of one head.
#define VP 66   // smem pitch (halves)
__global__ void k_rope_cvt2(const float* __restrict__ qkv,
                            __half* __restrict__ qh, __half* __restrict__ ql,
                            __half* __restrict__ kh,
                            __half* __restrict__ vth) {
    __shared__ __half vsh[64*VP];
    int tid = threadIdx.x;
    int qt = blockIdx.x, head = blockIdx.y, b = blockIdx.z;
    int t0 = qt * 64;

    #pragma unroll
    for (int it = 0; it < 8; ++it) {
        int e = tid + it*256;          // 0..2047 pairs
        int r = e >> 5;                // token row 0..63
        int i = e & 31;                // pair index
        int t = t0 + r;
        int m = b*TT + t;
        float invf = __powf(10000.0f, -(2.0f * i) / 64.0f);
        float ang  = (float)t * invf;
        float c, s;
        __sincosf(ang, &s, &c);

        size_t base = (size_t)m*(3*CC) + head*64 + i;
        size_t qo = (size_t)m*CC + head*64 + i;
        {
            float x1 = qkv[base], x2 = qkv[base+32];
            float r1 = (x1*c - x2*s) * 0.125f;
            float r2 = (x2*c + x1*s) * 0.125f;
            __half h1 = __float2half(r1), h2 = __float2half(r2);
            qh[qo]    = h1; ql[qo]    = __float2half(r1 - __half2float(h1));
            qh[qo+32] = h2; ql[qo+32] = __float2half(r2 - __half2float(h2));
        }
        {
            float x1 = qkv[base+CC], x2 = qkv[base+CC+32];
            kh[qo]    = __float2half(x1*c - x2*s);
            kh[qo+32] = __float2half(x2*c + x1*s);
        }
        {
            vsh[i*VP + r]      = __float2half(qkv[base+2*CC]);
            vsh[(i+32)*VP + r] = __float2half(qkv[base+2*CC+32]);
        }
    }
    __syncthreads();

    int d = tid >> 2;
    int rs = (tid & 3) * 16;
    size_t obase = ((size_t)(b*NHH + head)*DHH + d) * TT + t0 + rs;
    unsigned wh[8];
    #pragma unroll
    for (int j = 0; j < 8; ++j)
        wh[j] = packh2(vsh[d*VP + rs + 2*j], vsh[d*VP + rs + 2*j + 1]);
    uint4 o0, o1;
    o0.x = wh[0]; o0.y = wh[1]; o0.z = wh[2]; o0.w = wh[3];
    o1.x = wh[4]; o1.y = wh[5]; o1.z = wh[6]; o1.w = wh[7];
    *(uint4*)&vth[obase]     = o0;
    *(uint4*)&vth[obase + 8] = o1;
}

// ---------------- tensor-core flash attention (2-term, double-buffered) ------
// grid (T/64, NH, B), 128 threads; longest tiles scheduled first.
// QK = Qhi*Khi + Qlo*Khi;  PV = Phi*Vhi + Plo*Vhi  (Klo/Vlo dropped).
#define ASTG 9216               // halves per stage: 2 arrays * 64*72
#define ASMEM (2*ASTG*2)        // bytes = 36864
__global__ void k_attn_mma(const __half* __restrict__ qh, const __half* __restrict__ ql,
                           const __half* __restrict__ kh,
                           const __half* __restrict__ vth,
                           __half* __restrict__ y2) {
    extern __shared__ __half ash[];

    int tid = threadIdx.x, wid = tid >> 5, lane = tid & 31;
    int g = lane >> 2, t = lane & 3;
    int qt = (TT/64 - 1) - blockIdx.x;         // longest-first
    int head = blockIdx.y, b = blockIdx.z;

    auto load_tile = [&](int st, int kt) {
        __half* Kh = ash + st*ASTG;
        __half* Vh = Kh + 4608;
        #pragma unroll
        for (int i = 0; i < 4; ++i) {
            int cid = tid + i*128;
            int row = cid >> 3, ch = (cid & 7) * 8;
            size_t ksrc = (size_t)(b*TT + kt*64 + row)*CC + head*64 + ch;
            cp16(&Kh[row*72 + ch], kh + ksrc);
            size_t vsrc = ((size_t)(b*NHH + head)*DHH + row)*TT + kt*64 + ch;
            cp16(&Vh[row*72 + ch], vth + vsrc);
        }
    };

    unsigned aQh[4][4], aQl[4][4];
    {
        size_t r0 = (size_t)(b*TT + qt*64 + wid*16 + g) * CC + head*64;
        size_t r1 = r0 + 8*CC;
        #pragma unroll
        for (int ks = 0; ks < 4; ++ks) {
            int c0 = ks*16 + 2*t, c1 = c0 + 8;
            aQh[ks][0] = *(const unsigned*)&qh[r0 + c0];
            aQh[ks][1] = *(const unsigned*)&qh[r1 + c0];
            aQh[ks][2] = *(const unsigned*)&qh[r0 + c1];
            aQh[ks][3] = *(const unsigned*)&qh[r1 + c1];
            aQl[ks][0] = *(const unsigned*)&ql[r0 + c0];
            aQl[ks][1] = *(const unsigned*)&ql[r1 + c0];
            aQl[ks][2] = *(const unsigned*)&ql[r0 + c1];
            aQl[ks][3] = *(const unsigned*)&ql[r1 + c1];
        }
    }

    float O[8][4];
    #pragma unroll
    for (int n = 0; n < 8; ++n)
        #pragma unroll
        for (int q = 0; q < 4; ++q) O[n][q] = 0.f;
    float m0 = -INFINITY, m1 = -INFINITY, l0 = 0.f, l1 = 0.f;

    int st = 0;
    load_tile(0, 0);
    CP_COMMIT();

    for (int kt = 0; kt <= qt; ++kt) {
        if (kt + 1 <= qt) {
            load_tile(st ^ 1, kt + 1);
            CP_COMMIT();
            CP_WAIT(1);
        } else {
            CP_WAIT(0);
        }
        __syncthreads();

        __half* Kh = ash + st*ASTG;
        __half* Vh = Kh + 4608;

        float S[8][4];
        #pragma unroll
        for (int n = 0; n < 8; ++n) {
            S[n][0] = S[n][1] = S[n][2] = S[n][3] = 0.f;
            #pragma unroll
            for (int ks = 0; ks < 4; ++ks) {
                unsigned bh[2];
                bh[0] = *(const unsigned*)&Kh[(n*8+g)*72 + ks*16 + 2*t];
                bh[1] = *(const unsigned*)&Kh[(n*8+g)*72 + ks*16 + 2*t + 8];
                mma16816(S[n], aQh[ks], bh);
                mma16816(S[n], aQl[ks], bh);
            }
        }

        if (kt == qt) {
            int r0 = wid*16 + g, r1 = r0 + 8;
            #pragma unroll
            for (int n = 0; n < 8; ++n) {
                int c0 = n*8 + 2*t, c1 = c0 + 1;
                if (c0 > r0) S[n][0] = -INFINITY;
                if (c1 > r0) S[n][1] = -INFINITY;
                if (c0 > r1) S[n][2] = -INFINITY;
                if (c1 > r1) S[n][3] = -INFINITY;
            }
        }

        float mt0 = -INFINITY, mt1 = -INFINITY;
        #pragma unroll
        for (int n = 0; n < 8; ++n) {
            mt0 = fmaxf(mt0, fmaxf(S[n][0], S[n][1]));
            mt1 = fmaxf(mt1, fmaxf(S[n][2], S[n][3]));
        }
        mt0 = fmaxf(mt0, __shfl_xor_sync(0xffffffffu, mt0, 1));
        mt0 = fmaxf(mt0, __shfl_xor_sync(0xffffffffu, mt0, 2));
        mt1 = fmaxf(mt1, __shfl_xor_sync(0xffffffffu, mt1, 1));
        mt1 = fmaxf(mt1, __shfl_xor_sync(0xffffffffu, mt1, 2));
        float mn0 = fmaxf(m0, mt0), mn1 = fmaxf(m1, mt1);
        float a0 = __expf(m0 - mn0), a1 = __expf(m1 - mn1);
        float ls0 = 0.f, ls1 = 0.f;
        #pragma unroll
        for (int n = 0; n < 8; ++n) {
            S[n][0] = __expf(S[n][0] - mn0);
            S[n][1] = __expf(S[n][1] - mn0);
            S[n][2] = __expf(S[n][2] - mn1);
            S[n][3] = __expf(S[n][3] - mn1);
            ls0 += S[n][0] + S[n][1];
            ls1 += S[n][2] + S[n][3];
        }
        ls0 += __shfl_xor_sync(0xffffffffu, ls0, 1);
        ls0 += __shfl_xor_sync(0xffffffffu, ls0, 2);
        ls1 += __shfl_xor_sync(0xffffffffu, ls1, 1);
        ls1 += __shfl_xor_sync(0xffffffffu, ls1, 2);
        l0 = l0*a0 + ls0;  m0 = mn0;
        l1 = l1*a1 + ls1;  m1 = mn1;
        #pragma unroll
        for (int n = 0; n < 8; ++n) {
            O[n][0] *= a0; O[n][1] *= a0;
            O[n][2] *= a1; O[n][3] *= a1;
        }

        unsigned aPh[4][4], aPl[4][4];
        #pragma unroll
        for (int ks = 0; ks < 4; ++ks) {
            pack2(S[2*ks][0],   S[2*ks][1],   aPh[ks][0], aPl[ks][0]);
            pack2(S[2*ks][2],   S[2*ks][3],   aPh[ks][1], aPl[ks][1]);
            pack2(S[2*ks+1][0], S[2*ks+1][1], aPh[ks][2], aPl[ks][2]);
            pack2(S[2*ks+1][2], S[2*ks+1][3], aPh[ks][3], aPl[ks][3]);
        }

        #pragma unroll
        for (int n = 0; n < 8; ++n) {
            #pragma unroll
            for (int ks = 0; ks < 4; ++ks) {
                unsigned bh[2];
                bh[0] = *(const unsigned*)&Vh[(n*8+g)*72 + ks*16 + 2*t];
                bh[1] = *(const unsigned*)&Vh[(n*8+g)*72 + ks*16 + 2*t + 8];
                mma16816(O[n], aPh[ks], bh);
                mma16816(O[n], aPl[ks], bh);
            }
        }
        __syncthreads();
        st ^= 1;
    }

    float i0 = 1.f / l0, i1 = 1.f / l1;
    int row0 = b*TT + qt*64 + wid*16 + g;
    #pragma unroll
    for (int n = 0; n < 8; ++n) {
        int col = head*64 + n*8 + 2*t;
        float v0 = O[n][0]*i0, v1 = O[n][1]*i0;
        float v2 = O[n][2]*i1, v3 = O[n][3]*i1;
        unsigned h01, l01, h23, l23;
        pack2(v0, v1, h01, l01);
        pack2(v2, v3, h23, l23);
        *(unsigned*)&y2[(size_t)row0*2*CC + col]            = h01;
        *(unsigned*)&y2[(size_t)row0*2*CC + CC + col]       = l01;
        *(unsigned*)&y2[(size_t)(row0+8)*2*CC + col]        = h23;
        *(unsigned*)&y2[(size_t)(row0+8)*2*CC + CC + col]   = l23;
    }
}

// ---------------- final RMSNorm into d_out (vectorized) ----------------------
__global__ void k_rms_out4(const float* __restrict__ in,
                           float* __restrict__ out,
                           const float* __restrict__ g) {
    int m = blockIdx.x;
    int c4 = threadIdx.x * 4;
    float4 v = *(const float4*)&in[(size_t)m*CC + c4];
    float s = v.x*v.x + v.y*v.y + v.z*v.z + v.w*v.w;
    __shared__ float red[256];
    red[threadIdx.x] = s;
    __syncthreads();
    #pragma unroll
    for (int off = 128; off > 0; off >>= 1) {
        if (threadIdx.x < off) red[threadIdx.x] += red[threadIdx.x + off];
        __syncthreads();
    }
    float inv = rsqrtf(red[0] * (1.0f/CC) + 1e-5f);
    float4 gv = *(const float4*)&g[c4];
    float4 o;
    o.x = v.x*inv*gv.x; o.y = v.y*inv*gv.y;
    o.z = v.z*inv*gv.z; o.w = v.w*inv*gv.w;
    *(float4*)&out[(size_t)m*CC + c4] = o;
}

// ---------------- orchestration ----------------------------------------------
extern "C" void kernel_launch(void* const* d_in, const int* in_sizes, int n_in,
                              void* d_out, int out_size) {
    const float* x    = (const float*)d_in[0];
    const float* w_in = (const float*)d_in[1];
    const float* wq   = (const float*)d_in[2];
    const float* wkv  = (const float*)d_in[3];
    const float* wo   = (const float*)d_in[4];
    const float* w1   = (const float*)d_in[5];
    const float* w2   = (const float*)d_in[6];
    const float* w3   = (const float*)d_in[7];
    const float* g1   = (const float*)d_in[8];
    const float* g2   = (const float*)d_in[9];
    const float* gf   = (const float*)d_in[10];
    float* out = (float*)d_out;

    float *h, *qkvb, *u1;
    __half *a2, *y2, *u12, *wqkv2, *wo2, *w12, *w22, *w32;
    __half *qhp, *qlp, *khp, *vthp;
    cudaGetSymbolAddress((void**)&h,    g_h);
    cudaGetSymbolAddress((void**)&a2,   g_a2);
    cudaGetSymbolAddress((void**)&qkvb, g_qkv);
    cudaGetSymbolAddress((void**)&qhp,  g_qh);
    cudaGetSymbolAddress((void**)&qlp,  g_ql);
    cudaGetSymbolAddress((void**)&khp,  g_kh);
    cudaGetSymbolAddress((void**)&vthp, g_vth);
    cudaGetSymbolAddress((void**)&y2,   g_y2);
    cudaGetSymbolAddress((void**)&u1,   g_u1);
    cudaGetSymbolAddress((void**)&u12,  g_u12);
    cudaGetSymbolAddress((void**)&wqkv2,g_wqkv2);
    cudaGetSymbolAddress((void**)&wo2,  g_wo2);
    cudaGetSymbolAddress((void**)&w12,  g_w12);
    cudaGetSymbolAddress((void**)&w22,  g_w22);
    cudaGetSymbolAddress((void**)&w32,  g_w32);

    cudaFuncSetAttribute(k_hgemm<0>,
                         cudaFuncAttributeMaxDynamicSharedMemorySize, GSMEM);
    cudaFuncSetAttribute(k_hgemm<1>,
                         cudaFuncAttributeMaxDynamicSharedMemorySize, GSMEM);
    cudaFuncSetAttribute(k_hgemm<2>,
                         cudaFuncAttributeMaxDynamicSharedMemorySize, GSMEM);
    cudaFuncSetAttribute(k_attn_mma,
                         cudaFuncAttributeMaxDynamicSharedMemorySize, ASMEM);

    // weight splits (vectorized)
    {
        int n;
        n = LLAYERS*3*CC*CC/4;
        k_split_qkv_w4<<<(n+255)/256, 256>>>(wq, wkv, wqkv2);
        n = LLAYERS*CC*CC;
        k_split_w4<<<(n/4+255)/256, 256>>>(wo, wo2, n/4, CC);
        n = LLAYERS*HFF_*CC;
        k_split_w4<<<(n/4+255)/256, 256>>>(w1, w12, n/4, CC);
        k_split_w4<<<(n/4+255)/256, 256>>>(w2, w22, n/4, CC);
        n = LLAYERS*CC*HFF_;
        k_split_w4<<<(n/4+255)/256, 256>>>(w3, w32, n/4, HFF_);
    }

    k_input_proj<<<MM*CC/256, 256>>>(x, w_in, h);

    for (int l = 0; l < LLAYERS; ++l) {
        const __half* wqkv_l = wqkv2 + (size_t)l*3*CC*2*CC;
        const __half* wo_l   = wo2   + (size_t)l*CC*2*CC;
        const __half* w1_l   = w12   + (size_t)l*HFF_*2*CC;
        const __half* w2_l   = w22   + (size_t)l*HFF_*2*CC;
        const __half* w3_l   = w32   + (size_t)l*CC*2*HFF_;

        // --- attention block ---
        k_rms_h<<<MM, 256>>>(h, a2, g1 + l*CC);
        k_hgemm<0><<<dim3(24,16), 256, GSMEM>>>(a2, wqkv_l, qkvb, nullptr, nullptr,
                                                3*CC, CC);
        k_rope_cvt2<<<dim3(TT/64, NHH, BB), 256>>>(qkvb, qhp, qlp, khp, vthp);
        k_attn_mma<<<dim3(TT/64, NHH, BB), 128, ASMEM>>>(qhp, qlp, khp, vthp, y2);
        k_hgemm<1><<<dim3(8,16), 256, GSMEM>>>(y2, wo_l, h, nullptr, nullptr,
                                               CC, CC);

        // --- MLP block ---
        k_rms_h<<<MM, 256>>>(h, a2, g2 + l*CC);
        k_hgemm<0><<<dim3(22,16), 256, GSMEM>>>(a2, w1_l, u1, nullptr, nullptr,
                                                HFF_, CC);
        k_hgemm<2><<<dim3(22,16), 256, GSMEM>>>(a2, w2_l, nullptr, u1, u12,
                                                HFF_, CC);
        k_hgemm<1><<<dim3(8,16), 256, GSMEM>>>(u12, w3_l, h, nullptr, nullptr,
                                               CC, HFF_);
    }

    k_rms_out4<<<MM, 256>>>(h, out, gf);
}

// round 16
// speedup vs baseline: 1.5186x; 1.5186x over previous
#include <cuda_runtime.h>
#include <cuda_fp16.h>
#include <math.h>

#define BB   2
#define TT   1024
#define CC   1024
#define NHH  16
#define DHH  64
#define LLAYERS 4
#define HFF_ 2816
#define MM   (BB*TT)          // 2048 rows

// ---------------- scratch (static device globals) ---------------------------
__device__ __align__(16) float  g_h   [MM*CC];
__device__ __align__(16) __half g_a2  [MM*2*CC];     // rms acts [hi|lo]
__device__ __align__(16) float  g_qkv [MM*3*CC];     // fused q|k|v (fp32)
__device__ __align__(16) __half g_qh  [MM*CC];       // roped q hi (pre-scaled)
__device__ __align__(16) __half g_ql  [MM*CC];
__device__ __align__(16) __half g_kh  [MM*CC];
__device__ __align__(16) __half g_vth [MM*CC];       // V^T [b][h][d][t] hi
__device__ __align__(16) __half g_y2  [MM*2*CC];     // attn out [hi|lo]
__device__ __align__(16) float  g_u1  [MM*HFF_];
__device__ __align__(16) __half g_u12 [MM*2*HFF_];

// split fp16 weights, row layout [row][hi(K) | lo(K)]
__device__ __align__(16) __half g_wqkv2[LLAYERS*3*CC*2*CC];
__device__ __align__(16) __half g_wo2  [LLAYERS*CC*2*CC];
__device__ __align__(16) __half g_w12  [LLAYERS*HFF_*2*CC];
__device__ __align__(16) __half g_w22  [LLAYERS*HFF_*2*CC];
__device__ __align__(16) __half g_w32  [LLAYERS*CC*2*HFF_];

// ---------------- helpers ----------------------------------------------------
__device__ __forceinline__ void cp16(void* smem_dst, const void* gsrc) {
    unsigned d = (unsigned)__cvta_generic_to_shared(smem_dst);
    asm volatile("cp.async.ca.shared.global [%0], [%1], 16;\n" :: "r"(d), "l"(gsrc));
}
#define CP_COMMIT()  asm volatile("cp.async.commit_group;\n")
#define CP_WAIT(N)   asm volatile("cp.async.wait_group %0;\n" :: "n"(N))

__device__ __forceinline__ void mma16816(float* d, const unsigned* a, const unsigned* b) {
    asm volatile(
        "mma.sync.aligned.m16n8k16.row.col.f32.f16.f16.f32 "
        "{%0,%1,%2,%3}, {%4,%5,%6,%7}, {%8,%9}, {%0,%1,%2,%3};\n"
        : "+f"(d[0]), "+f"(d[1]), "+f"(d[2]), "+f"(d[3])
        : "r"(a[0]), "r"(a[1]), "r"(a[2]), "r"(a[3]), "r"(b[0]), "r"(b[1]));
}

__device__ __forceinline__ void ldsm4(unsigned addr, unsigned& r0, unsigned& r1,
                                      unsigned& r2, unsigned& r3) {
    asm volatile("ldmatrix.sync.aligned.m8n8.x4.shared.b16 {%0,%1,%2,%3}, [%4];\n"
                 : "=r"(r0), "=r"(r1), "=r"(r2), "=r"(r3) : "r"(addr));
}

__device__ __forceinline__ unsigned packh2(__half a, __half b) {
    return (unsigned)__half_as_ushort(a) | ((unsigned)__half_as_ushort(b) << 16);
}
__device__ __forceinline__ void pack2(float x, float y, unsigned& hi, unsigned& lo) {
    __half hx = __float2half(x), hy = __float2half(y);
    __half lx = __float2half(x - __half2float(hx));
    __half ly = __float2half(y - __half2float(hy));
    hi = packh2(hx, hy);
    lo = packh2(lx, ly);
}

// ---------------- weight split conversion (vectorized) -----------------------
__global__ void k_split_w4(const float* __restrict__ src, __half* __restrict__ dst,
                           int total4, int K) {
    int idx = blockIdx.x * blockDim.x + threadIdx.x;
    if (idx >= total4) return;
    int i4 = idx * 4;
    int r = i4 / K;
    int k = i4 - r * K;
    float4 v = *(const float4*)&src[i4];
    __half h0 = __float2half(v.x), h1 = __float2half(v.y);
    __half h2 = __float2half(v.z), h3 = __float2half(v.w);
    __half l0 = __float2half(v.x - __half2float(h0));
    __half l1 = __float2half(v.y - __half2float(h1));
    __half l2 = __float2half(v.z - __half2float(h2));
    __half l3 = __float2half(v.w - __half2float(h3));
    size_t off = (size_t)r*2*K + k;
    uint2 uh; uh.x = packh2(h0,h1); uh.y = packh2(h2,h3);
    uint2 ul; ul.x = packh2(l0,l1); ul.y = packh2(l2,l3);
    *(uint2*)&dst[off]     = uh;
    *(uint2*)&dst[off + K] = ul;
}

__global__ void k_split_qkv_w4(const float* __restrict__ wq,
                               const float* __restrict__ wkv,
                               __half* __restrict__ dst) {
    int idx = blockIdx.x * blockDim.x + threadIdx.x;
    if (idx >= LLAYERS*3*CC*CC/4) return;
    int i4  = idx * 4;
    int l   = i4 / (3*CC*CC);
    int rem = i4 - l*(3*CC*CC);
    int row = rem >> 10;
    int k   = rem & 1023;
    float4 v = (row < CC)
        ? *(const float4*)&wq [((size_t)l*CC   + row)      * CC + k]
        : *(const float4*)&wkv[((size_t)l*2*CC + (row-CC)) * CC + k];
    __half h0 = __float2half(v.x), h1 = __float2half(v.y);
    __half h2 = __float2half(v.z), h3 = __float2half(v.w);
    __half l0 = __float2half(v.x - __half2float(h0));
    __half l1 = __float2half(v.y - __half2float(h1));
    __half l2 = __float2half(v.z - __half2float(h2));
    __half l3 = __float2half(v.w - __half2float(h3));
    __half* d = dst + ((size_t)l*3*CC + row)*2*CC;
    uint2 uh; uh.x = packh2(h0,h1); uh.y = packh2(h2,h3);
    uint2 ul; ul.x = packh2(l0,l1); ul.y = packh2(l2,l3);
    *(uint2*)&d[k]      = uh;
    *(uint2*)&d[CC + k] = ul;
}

// ---------------- input projection: h = x @ w_in^T  (K=9) --------------------
__global__ void k_input_proj(const float* __restrict__ x,
                             const float* __restrict__ w,
                             float* __restrict__ h) {
    int idx = blockIdx.x * blockDim.x + threadIdx.x;
    if (idx >= MM*CC) return;
    int m = idx >> 10;
    int c = idx & 1023;
    const float* xr = x + m*9;
    const float* wr = w + c*9;
    float s = 0.f;
    #pragma unroll
    for (int f = 0; f < 9; ++f) s += xr[f] * wr[f];
    h[idx] = s;
}

// ---------------- RMSNorm -> split fp16 hi/lo (vectorized) -------------------
__global__ void k_rms_h(const float* __restrict__ in,
                        __half* __restrict__ out2,     // [M][2C]
                        const float* __restrict__ g) {
    int m = blockIdx.x;
    int c4 = threadIdx.x * 4;
    float4 v = *(const float4*)&in[(size_t)m*CC + c4];
    float s = v.x*v.x + v.y*v.y + v.z*v.z + v.w*v.w;
    __shared__ float red[256];
    red[threadIdx.x] = s;
    __syncthreads();
    #pragma unroll
    for (int off = 128; off > 0; off >>= 1) {
        if (threadIdx.x < off) red[threadIdx.x] += red[threadIdx.x + off];
        __syncthreads();
    }
    float inv = rsqrtf(red[0] * (1.0f/CC) + 1e-5f);
    float4 gv = *(const float4*)&g[c4];
    float o0 = v.x*inv*gv.x, o1 = v.y*inv*gv.y;
    float o2 = v.z*inv*gv.z, o3 = v.w*inv*gv.w;
    unsigned h01, l01, h23, l23;
    pack2(o0, o1, h01, l01);
    pack2(o2, o3, h23, l23);
    uint2 uh; uh.x = h01; uh.y = h23;
    uint2 ul; ul.x = l01; ul.y = l23;
    *(uint2*)&out2[(size_t)m*2*CC + c4]      = uh;
    *(uint2*)&out2[(size_t)m*2*CC + CC + c4] = ul;
}

// ---------------- 3-stage pipelined ldmatrix fp16x3 tensor-core GEMM ---------
// C[M,N] (+)= A[M,K]*W[N,K]^T as Ahi*Whi + Alo*Whi + Ahi*Wlo, single K pass.
// BM=BN=128, BK=32, 256 threads (8 warps, 4m x 2n, 32x64 warp tile).
// EPI: 0 = store fp32, 1 = add into fp32, 2 = silu(aux)*acc -> hi/lo fp16 out2.
#define GSTG 20480            // halves per stage (512 rows * 40)
#define GSMEM (3*GSTG*2)      // bytes = 122880
template<int EPI>
__global__ void __launch_bounds__(256, 1)
k_hgemm(const __half* __restrict__ A,
        const __half* __restrict__ W,
        float* __restrict__ C,
        const float* __restrict__ aux,
        __half* __restrict__ out2,
        int N, int K) {
    extern __shared__ __half sh[];
    int tid  = threadIdx.x;
    int wid  = tid >> 5, lane = tid & 31;
    int wm   = wid & 3,  wn   = wid >> 2;
    int g    = lane >> 2, t   = lane & 3;
    int m0   = blockIdx.y * 128, n0 = blockIdx.x * 128;
    int ld   = 2 * K;
    const int IT = K / 32;

    unsigned sb = (unsigned)__cvta_generic_to_shared(sh);
    unsigned aOff = (lane & 15)*80 + (lane >> 4)*16;
    unsigned bOff = ((lane & 7) + ((lane >> 4) << 3))*80 + ((lane >> 3) & 1)*16;

    float acc[2][8][4];
    #pragma unroll
    for (int mi = 0; mi < 2; ++mi)
        #pragma unroll
        for (int ni = 0; ni < 8; ++ni)
            #pragma unroll
            for (int q = 0; q < 4; ++q) acc[mi][ni][q] = 0.f;

    auto load_stage = [&](int st, int k0) {
        __half* base = sh + st*GSTG;
        #pragma unroll
        for (int i = 0; i < 8; ++i) {
            int c   = tid + i*256;
            int row = c >> 2;
            int kc  = (c & 3) * 8;
            const __half* src;
            if      (row < 128) src = A + (size_t)(m0 + row      )*ld + k0 + kc;
            else if (row < 256) src = A + (size_t)(m0 + row - 128)*ld + K + k0 + kc;
            else if (row < 384) src = W + (size_t)(n0 + row - 256)*ld + k0 + kc;
            else                src = W + (size_t)(n0 + row - 384)*ld + K + k0 + kc;
            cp16(base + row*40 + kc, src);
        }
    };

    auto compute_stage = [&](int st) {
        unsigned base = sb + st*(GSTG*2);
        unsigned aHb = base + (wm*32)*80 + aOff;
        unsigned aLb = aHb + 128*80;
        unsigned bHb = base + 256*80 + (wn*64)*80 + bOff;
        unsigned bLb = bHb + 128*80;
        #pragma unroll
        for (int kk = 0; kk < 32; kk += 16) {
            unsigned aH[2][4], aL[2][4], bh[8][2], bl[8][2];
            #pragma unroll
            for (int mi = 0; mi < 2; ++mi) {
                ldsm4(aHb + mi*16*80 + kk*2, aH[mi][0], aH[mi][1], aH[mi][2], aH[mi][3]);
                ldsm4(aLb + mi*16*80 + kk*2, aL[mi][0], aL[mi][1], aL[mi][2], aL[mi][3]);
            }
            #pragma unroll
            for (int nj = 0; nj < 4; ++nj) {
                ldsm4(bHb + nj*16*80 + kk*2,
                      bh[2*nj][0], bh[2*nj][1], bh[2*nj+1][0], bh[2*nj+1][1]);
                ldsm4(bLb + nj*16*80 + kk*2,
                      bl[2*nj][0], bl[2*nj][1], bl[2*nj+1][0], bl[2*nj+1][1]);
            }
            #pragma unroll
            for (int ni = 0; ni < 8; ++ni)
                #pragma unroll
                for (int mi = 0; mi < 2; ++mi) {
                    mma16816(acc[mi][ni], aH[mi], bh[ni]);
                    mma16816(acc[mi][ni], aL[mi], bh[ni]);
                    mma16816(acc[mi][ni], aH[mi], bl[ni]);
                }
        }
    };

    load_stage(0, 0);  CP_COMMIT();
    load_stage(1, 32); CP_COMMIT();
    for (int it = 0; it < IT; ++it) {
        CP_WAIT(1);
        __syncthreads();
        if (it + 2 < IT) load_stage((it+2)%3, (it+2)*32);
        CP_COMMIT();
        compute_stage(it % 3);
    }

    #pragma unroll
    for (int mi = 0; mi < 2; ++mi)
        #pragma unroll
        for (int ni = 0; ni < 8; ++ni) {
            int row = m0 + wm*32 + mi*16 + g;
            int col = n0 + wn*64 + ni*8 + 2*t;
            if (EPI == 0) {
                *(float2*)&C[(size_t)row*N + col] =
                    make_float2(acc[mi][ni][0], acc[mi][ni][1]);
                *(float2*)&C[(size_t)(row + 8)*N + col] =
                    make_float2(acc[mi][ni][2], acc[mi][ni][3]);
            } else if (EPI == 1) {
                float2* p0 = (float2*)&C[(size_t)row*N + col];
                float2* p1 = (float2*)&C[(size_t)(row + 8)*N + col];
                float2 v0 = *p0, v1 = *p1;
                v0.x += acc[mi][ni][0]; v0.y += acc[mi][ni][1];
                v1.x += acc[mi][ni][2]; v1.y += acc[mi][ni][3];
                *p0 = v0; *p1 = v1;
            } else {
                float2 a0v = *(const float2*)&aux[(size_t)row*N + col];
                float2 a1v = *(const float2*)&aux[(size_t)(row+8)*N + col];
                float v0 = a0v.x / (1.f + __expf(-a0v.x)) * acc[mi][ni][0];
                float v1 = a0v.y / (1.f + __expf(-a0v.y)) * acc[mi][ni][1];
                float v2 = a1v.x / (1.f + __expf(-a1v.x)) * acc[mi][ni][2];
                float v3 = a1v.y / (1.f + __expf(-a1v.y)) * acc[mi][ni][3];
                unsigned h01, l01, h23, l23;
                pack2(v0, v1, h01, l01);
                pack2(v2, v3, h23, l23);
                *(unsigned*)&out2[(size_t)row*2*N + col]          = h01;
                *(unsigned*)&out2[(size_t)row*2*N + N + col]      = l01;
                *(unsigned*)&out2[(size_t)(row+8)*2*N + col]      = h23;
                *(unsigned*)&out2[(size_t)(row+8)*2*N + N + col]  = l23;
            }
        }
}

// ---------------- RoPE + convert (tile-based, coalesced V^T, hi-only K/V) ----
// grid (TT/64, NH, B), 256 threads. Each CTA: 64 tokens x 64 dims of one head.
#define VP 66   // smem pitch (halves)
__global__ void k_rope_cvt2(const float* __restrict__ qkv,
                            __half* __restrict__ qh, __half* __restrict__ ql,
                            __half* __restrict__ kh,
                            __half* __restrict__ vth) {
    __shared__ __half vsh[64*VP];
    int tid = threadIdx.x;
    int qt = blockIdx.x, head = blockIdx.y, b = blockIdx.z;
    int t0 = qt * 64;

    #pragma unroll
    for (int it = 0; it < 8; ++it) {
        int e = tid + it*256;          // 0..2047 pairs
        int r = e >> 5;                // token row 0..63
        int i = e & 31;                // pair index
        int t = t0 + r;
        int m = b*TT + t;
        float invf = __powf(10000.0f, -(2.0f * i) / 64.0f);
        float ang  = (float)t * invf;
        float c, s;
        __sincosf(ang, &s, &c);

        size_t base = (size_t)m*(3*CC) + head*64 + i;
        size_t qo = (size_t)m*CC + head*64 + i;
        {
            float x1 = qkv[base], x2 = qkv[base+32];
            float r1 = (x1*c - x2*s) * 0.125f;
            float r2 = (x2*c + x1*s) * 0.125f;
            __half h1 = __float2half(r1), h2 = __float2half(r2);
            qh[qo]    = h1; ql[qo]    = __float2half(r1 - __half2float(h1));
            qh[qo+32] = h2; ql[qo+32] = __float2half(r2 - __half2float(h2));
        }
        {
            float x1 = qkv[base+CC], x2 = qkv[base+CC+32];
            kh[qo]    = __float2half(x1*c - x2*s);
            kh[qo+32] = __float2half(x2*c + x1*s);
        }
        {
            vsh[i*VP + r]      = __float2half(qkv[base+2*CC]);
            vsh[(i+32)*VP + r] = __float2half(qkv[base+2*CC+32]);
        }
    }
    __syncthreads();

    int d = tid >> 2;
    int rs = (tid & 3) * 16;
    size_t obase = ((size_t)(b*NHH + head)*DHH + d) * TT + t0 + rs;
    unsigned wh[8];
    #pragma unroll
    for (int j = 0; j < 8; ++j)
        wh[j] = packh2(vsh[d*VP + rs + 2*j], vsh[d*VP + rs + 2*j + 1]);
    uint4 o0, o1;
    o0.x = wh[0]; o0.y = wh[1]; o0.z = wh[2]; o0.w = wh[3];
    o1.x = wh[4]; o1.y = wh[5]; o1.z = wh[6]; o1.w = wh[7];
    *(uint4*)&vth[obase]     = o0;
    *(uint4*)&vth[obase + 8] = o1;
}

// ---------------- tensor-core flash attention (2-term, double-buffered) ------
// grid (T/64, NH, B), 128 threads; longest tiles scheduled first.
// QK = Qhi*Khi + Qlo*Khi;  PV = Phi*Vhi + Plo*Vhi  (Klo/Vlo dropped).
#define ASTG 9216               // halves per stage: 2 arrays * 64*72
#define ASMEM (2*ASTG*2)        // bytes = 36864
__global__ void k_attn_mma(const __half* __restrict__ qh, const __half* __restrict__ ql,
                           const __half* __restrict__ kh,
                           const __half* __restrict__ vth,
                           __half* __restrict__ y2) {
    extern __shared__ __half ash[];

    int tid = threadIdx.x, wid = tid >> 5, lane = tid & 31;
    int g = lane >> 2, t = lane & 3;
    int qt = (TT/64 - 1) - blockIdx.x;         // longest-first
    int head = blockIdx.y, b = blockIdx.z;

    auto load_tile = [&](int st, int kt) {
        __half* Kh = ash + st*ASTG;
        __half* Vh = Kh + 4608;
        #pragma unroll
        for (int i = 0; i < 4; ++i) {
            int cid = tid + i*128;
            int row = cid >> 3, ch = (cid & 7) * 8;
            size_t ksrc = (size_t)(b*TT + kt*64 + row)*CC + head*64 + ch;
            cp16(&Kh[row*72 + ch], kh + ksrc);
            size_t vsrc = ((size_t)(b*NHH + head)*DHH + row)*TT + kt*64 + ch;
            cp16(&Vh[row*72 + ch], vth + vsrc);
        }
    };

    unsigned aQh[4][4], aQl[4][4];
    {
        size_t r0 = (size_t)(b*TT + qt*64 + wid*16 + g) * CC + head*64;
        size_t r1 = r0 + 8*CC;
        #pragma unroll
        for (int ks = 0; ks < 4; ++ks) {
            int c0 = ks*16 + 2*t, c1 = c0 + 8;
            aQh[ks][0] = *(const unsigned*)&qh[r0 + c0];
            aQh[ks][1] = *(const unsigned*)&qh[r1 + c0];
            aQh[ks][2] = *(const unsigned*)&qh[r0 + c1];
            aQh[ks][3] = *(const unsigned*)&qh[r1 + c1];
            aQl[ks][0] = *(const unsigned*)&ql[r0 + c0];
            aQl[ks][1] = *(const unsigned*)&ql[r1 + c0];
            aQl[ks][2] = *(const unsigned*)&ql[r0 + c1];
            aQl[ks][3] = *(const unsigned*)&ql[r1 + c1];
        }
    }

    float O[8][4];
    #pragma unroll
    for (int n = 0; n < 8; ++n)
        #pragma unroll
        for (int q = 0; q < 4; ++q) O[n][q] = 0.f;
    float m0 = -INFINITY, m1 = -INFINITY, l0 = 0.f, l1 = 0.f;

    int st = 0;
    load_tile(0, 0);
    CP_COMMIT();

    for (int kt = 0; kt <= qt; ++kt) {
        if (kt + 1 <= qt) {
            load_tile(st ^ 1, kt + 1);
            CP_COMMIT();
            CP_WAIT(1);
        } else {
            CP_WAIT(0);
        }
        __syncthreads();

        __half* Kh = ash + st*ASTG;
        __half* Vh = Kh + 4608;

        float S[8][4];
        #pragma unroll
        for (int n = 0; n < 8; ++n) {
            S[n][0] = S[n][1] = S[n][2] = S[n][3] = 0.f;
            #pragma unroll
            for (int ks = 0; ks < 4; ++ks) {
                unsigned bh[2];
                bh[0] = *(const unsigned*)&Kh[(n*8+g)*72 + ks*16 + 2*t];
                bh[1] = *(const unsigned*)&Kh[(n*8+g)*72 + ks*16 + 2*t + 8];
                mma16816(S[n], aQh[ks], bh);
                mma16816(S[n], aQl[ks], bh);
            }
        }

        if (kt == qt) {
            int r0 = wid*16 + g, r1 = r0 + 8;
            #pragma unroll
            for (int n = 0; n < 8; ++n) {
                int c0 = n*8 + 2*t, c1 = c0 + 1;
                if (c0 > r0) S[n][0] = -INFINITY;
                if (c1 > r0) S[n][1] = -INFINITY;
                if (c0 > r1) S[n][2] = -INFINITY;
                if (c1 > r1) S[n][3] = -INFINITY;
            }
        }

        float mt0 = -INFINITY, mt1 = -INFINITY;
        #pragma unroll
        for (int n = 0; n < 8; ++n) {
            mt0 = fmaxf(mt0, fmaxf(S[n][0], S[n][1]));
            mt1 = fmaxf(mt1, fmaxf(S[n][2], S[n][3]));
        }
        mt0 = fmaxf(mt0, __shfl_xor_sync(0xffffffffu, mt0, 1));
        mt0 = fmaxf(mt0, __shfl_xor_sync(0xffffffffu, mt0, 2));
        mt1 = fmaxf(mt1, __shfl_xor_sync(0xffffffffu, mt1, 1));
        mt1 = fmaxf(mt1, __shfl_xor_sync(0xffffffffu, mt1, 2));
        float mn0 = fmaxf(m0, mt0), mn1 = fmaxf(m1, mt1);
        float a0 = __expf(m0 - mn0), a1 = __expf(m1 - mn1);
        float ls0 = 0.f, ls1 = 0.f;
        #pragma unroll
        for (int n = 0; n < 8; ++n) {
            S[n][0] = __expf(S[n][0] - mn0);
            S[n][1] = __expf(S[n][1] - mn0);
            S[n][2] = __expf(S[n][2] - mn1);
            S[n][3] = __expf(S[n][3] - mn1);
            ls0 += S[n][0] + S[n][1];
            ls1 += S[n][2] + S[n][3];
        }
        ls0 += __shfl_xor_sync(0xffffffffu, ls0, 1);
        ls0 += __shfl_xor_sync(0xffffffffu, ls0, 2);
        ls1 += __shfl_xor_sync(0xffffffffu, ls1, 1);
        ls1 += __shfl_xor_sync(0xffffffffu, ls1, 2);
        l0 = l0*a0 + ls0;  m0 = mn0;
        l1 = l1*a1 + ls1;  m1 = mn1;
        #pragma unroll
        for (int n = 0; n < 8; ++n) {
            O[n][0] *= a0; O[n][1] *= a0;
            O[n][2] *= a1; O[n][3] *= a1;
        }

        unsigned aPh[4][4], aPl[4][4];
        #pragma unroll
        for (int ks = 0; ks < 4; ++ks) {
            pack2(S[2*ks][0],   S[2*ks][1],   aPh[ks][0], aPl[ks][0]);
            pack2(S[2*ks][2],   S[2*ks][3],   aPh[ks][1], aPl[ks][1]);
            pack2(S[2*ks+1][0], S[2*ks+1][1], aPh[ks][2], aPl[ks][2]);
            pack2(S[2*ks+1][2], S[2*ks+1][3], aPh[ks][3], aPl[ks][3]);
        }

        #pragma unroll
        for (int n = 0; n < 8; ++n) {
            #pragma unroll
            for (int ks = 0; ks < 4; ++ks) {
                unsigned bh[2];
                bh[0] = *(const unsigned*)&Vh[(n*8+g)*72 + ks*16 + 2*t];
                bh[1] = *(const unsigned*)&Vh[(n*8+g)*72 + ks*16 + 2*t + 8];
                mma16816(O[n], aPh[ks], bh);
                mma16816(O[n], aPl[ks], bh);
            }
        }
        __syncthreads();
        st ^= 1;
    }

    float i0 = 1.f / l0, i1 = 1.f / l1;
    int row0 = b*TT + qt*64 + wid*16 + g;
    #pragma unroll
    for (int n = 0; n < 8; ++n) {
        int col = head*64 + n*8 + 2*t;
        float v0 = O[n][0]*i0, v1 = O[n][1]*i0;
        float v2 = O[n][2]*i1, v3 = O[n][3]*i1;
        unsigned h01, l01, h23, l23;
        pack2(v0, v1, h01, l01);
        pack2(v2, v3, h23, l23);
        *(unsigned*)&y2[(size_t)row0*2*CC + col]            = h01;
        *(unsigned*)&y2[(size_t)row0*2*CC + CC + col]       = l01;
        *(unsigned*)&y2[(size_t)(row0+8)*2*CC + col]        = h23;
        *(unsigned*)&y2[(size_t)(row0+8)*2*CC + CC + col]   = l23;
    }
}

// ---------------- final RMSNorm into d_out (vectorized) ----------------------
__global__ void k_rms_out4(const float* __restrict__ in,
                           float* __restrict__ out,
                           const float* __restrict__ g) {
    int m = blockIdx.x;
    int c4 = threadIdx.x * 4;
    float4 v = *(const float4*)&in[(size_t)m*CC + c4];
    float s = v.x*v.x + v.y*v.y + v.z*v.z + v.w*v.w;
    __shared__ float red[256];
    red[threadIdx.x] = s;
    __syncthreads();
    #pragma unroll
    for (int off = 128; off > 0; off >>= 1) {
        if (threadIdx.x < off) red[threadIdx.x] += red[threadIdx.x + off];
        __syncthreads();
    }
    float inv = rsqrtf(red[0] * (1.0f/CC) + 1e-5f);
    float4 gv = *(const float4*)&g[c4];
    float4 o;
    o.x = v.x*inv*gv.x; o.y = v.y*inv*gv.y;
    o.z = v.z*inv*gv.z; o.w = v.w*inv*gv.w;
    *(float4*)&out[(size_t)m*CC + c4] = o;
}

// ---------------- orchestration ----------------------------------------------
extern "C" void kernel_launch(void* const* d_in, const int* in_sizes, int n_in,
                              void* d_out, int out_size) {
    const float* x    = (const float*)d_in[0];
    const float* w_in = (const float*)d_in[1];
    const float* wq   = (const float*)d_in[2];
    const float* wkv  = (const float*)d_in[3];
    const float* wo   = (const float*)d_in[4];
    const float* w1   = (const float*)d_in[5];
    const float* w2   = (const float*)d_in[6];
    const float* w3   = (const float*)d_in[7];
    const float* g1   = (const float*)d_in[8];
    const float* g2   = (const float*)d_in[9];
    const float* gf   = (const float*)d_in[10];
    float* out = (float*)d_out;

    float *h, *qkvb, *u1;
    __half *a2, *y2, *u12, *wqkv2, *wo2, *w12, *w22, *w32;
    __half *qhp, *qlp, *khp, *vthp;
    cudaGetSymbolAddress((void**)&h,    g_h);
    cudaGetSymbolAddress((void**)&a2,   g_a2);
    cudaGetSymbolAddress((void**)&qkvb, g_qkv);
    cudaGetSymbolAddress((void**)&qhp,  g_qh);
    cudaGetSymbolAddress((void**)&qlp,  g_ql);
    cudaGetSymbolAddress((void**)&khp,  g_kh);
    cudaGetSymbolAddress((void**)&vthp, g_vth);
    cudaGetSymbolAddress((void**)&y2,   g_y2);
    cudaGetSymbolAddress((void**)&u1,   g_u1);
    cudaGetSymbolAddress((void**)&u12,  g_u12);
    cudaGetSymbolAddress((void**)&wqkv2,g_wqkv2);
    cudaGetSymbolAddress((void**)&wo2,  g_wo2);
    cudaGetSymbolAddress((void**)&w12,  g_w12);
    cudaGetSymbolAddress((void**)&w22,  g_w22);
    cudaGetSymbolAddress((void**)&w32,  g_w32);

    cudaFuncSetAttribute(k_hgemm<0>,
                         cudaFuncAttributeMaxDynamicSharedMemorySize, GSMEM);
    cudaFuncSetAttribute(k_hgemm<1>,
                         cudaFuncAttributeMaxDynamicSharedMemorySize, GSMEM);
    cudaFuncSetAttribute(k_hgemm<2>,
                         cudaFuncAttributeMaxDynamicSharedMemorySize, GSMEM);
    cudaFuncSetAttribute(k_attn_mma,
                         cudaFuncAttributeMaxDynamicSharedMemorySize, ASMEM);

    // weight splits (vectorized)
    {
        int n;
        n = LLAYERS*3*CC*CC/4;
        k_split_qkv_w4<<<(n+255)/256, 256>>>(wq, wkv, wqkv2);
        n = LLAYERS*CC*CC;
        k_split_w4<<<(n/4+255)/256, 256>>>(wo, wo2, n/4, CC);
        n = LLAYERS*HFF_*CC;
        k_split_w4<<<(n/4+255)/256, 256>>>(w1, w12, n/4, CC);
        k_split_w4<<<(n/4+255)/256, 256>>>(w2, w22, n/4, CC);
        n = LLAYERS*CC*HFF_;
        k_split_w4<<<(n/4+255)/256, 256>>>(w3, w32, n/4, HFF_);
    }

    k_input_proj<<<MM*CC/256, 256>>>(x, w_in, h);

    for (int l = 0; l < LLAYERS; ++l) {
        const __half* wqkv_l = wqkv2 + (size_t)l*3*CC*2*CC;
        const __half* wo_l   = wo2   + (size_t)l*CC*2*CC;
        const __half* w1_l   = w12   + (size_t)l*HFF_*2*CC;
        const __half* w2_l   = w22   + (size_t)l*HFF_*2*CC;
        const __half* w3_l   = w32   + (size_t)l*CC*2*HFF_;

        // --- attention block ---
        k_rms_h<<<MM, 256>>>(h, a2, g1 + l*CC);
        k_hgemm<0><<<dim3(24,16), 256, GSMEM>>>(a2, wqkv_l, qkvb, nullptr, nullptr,
                                                3*CC, CC);
        k_rope_cvt2<<<dim3(TT/64, NHH, BB), 256>>>(qkvb, qhp, qlp, khp, vthp);
        k_attn_mma<<<dim3(TT/64, NHH, BB), 128, ASMEM>>>(qhp, qlp, khp, vthp, y2);
        k_hgemm<1><<<dim3(8,16), 256, GSMEM>>>(y2, wo_l, h, nullptr, nullptr,
                                               CC, CC);

        // --- MLP block ---
        k_rms_h<<<MM, 256>>>(h, a2, g2 + l*CC);
        k_hgemm<0><<<dim3(22,16), 256, GSMEM>>>(a2, w1_l, u1, nullptr, nullptr,
                                                HFF_, CC);
        k_hgemm<2><<<dim3(22,16), 256, GSMEM>>>(a2, w2_l, nullptr, u1, u12,
                                                HFF_, CC);
        k_hgemm<1><<<dim3(8,16), 256, GSMEM>>>(u12, w3_l, h, nullptr, nullptr,
                                               CC, HFF_);
    }

    k_rms_out4<<<MM, 256>>>(h, out, gf);
}

// round 17
// speedup vs baseline: 1.5749x; 1.0371x over previous
#include <cuda_runtime.h>
#include <cuda_fp16.h>
#include <math.h>

#define BB   2
#define TT   1024
#define CC   1024
#define NHH  16
#define DHH  64
#define LLAYERS 4
#define HFF_ 2816
#define MM   (BB*TT)          // 2048 rows

// ---------------- scratch (static device globals) ---------------------------
__device__ __align__(16) float  g_h   [MM*CC];
__device__ __align__(16) __half g_a2  [MM*2*CC];     // rms acts [hi|lo]
__device__ __align__(16) float  g_qkv [MM*3*CC];     // fused q|k|v (fp32)
__device__ __align__(16) __half g_qh  [MM*CC];       // roped q hi (pre-scaled)
__device__ __align__(16) __half g_ql  [MM*CC];
__device__ __align__(16) __half g_kh  [MM*CC];
__device__ __align__(16) __half g_vth [MM*CC];       // V^T [b][h][d][t] hi
__device__ __align__(16) __half g_y2  [MM*2*CC];     // attn out [hi|lo]
__device__ __align__(16) float  g_u1  [MM*HFF_];
__device__ __align__(16) __half g_u12 [MM*2*HFF_];

// split fp16 weights, row layout [row][hi(K) | lo(K)]
__device__ __align__(16) __half g_wqkv2[LLAYERS*3*CC*2*CC];
__device__ __align__(16) __half g_wo2  [LLAYERS*CC*2*CC];
__device__ __align__(16) __half g_w12  [LLAYERS*HFF_*2*CC];
__device__ __align__(16) __half g_w22  [LLAYERS*HFF_*2*CC];
__device__ __align__(16) __half g_w32  [LLAYERS*CC*2*HFF_];

// ---------------- helpers ----------------------------------------------------
__device__ __forceinline__ void cp16(void* smem_dst, const void* gsrc) {
    unsigned d = (unsigned)__cvta_generic_to_shared(smem_dst);
    asm volatile("cp.async.ca.shared.global [%0], [%1], 16;\n" :: "r"(d), "l"(gsrc));
}
#define CP_COMMIT()  asm volatile("cp.async.commit_group;\n")
#define CP_WAIT(N)   asm volatile("cp.async.wait_group %0;\n" :: "n"(N))

__device__ __forceinline__ void mma16816(float* d, const unsigned* a, const unsigned* b) {
    asm volatile(
        "mma.sync.aligned.m16n8k16.row.col.f32.f16.f16.f32 "
        "{%0,%1,%2,%3}, {%4,%5,%6,%7}, {%8,%9}, {%0,%1,%2,%3};\n"
        : "+f"(d[0]), "+f"(d[1]), "+f"(d[2]), "+f"(d[3])
        : "r"(a[0]), "r"(a[1]), "r"(a[2]), "r"(a[3]), "r"(b[0]), "r"(b[1]));
}

__device__ __forceinline__ void ldsm4(unsigned addr, unsigned& r0, unsigned& r1,
                                      unsigned& r2, unsigned& r3) {
    asm volatile("ldmatrix.sync.aligned.m8n8.x4.shared.b16 {%0,%1,%2,%3}, [%4];\n"
                 : "=r"(r0), "=r"(r1), "=r"(r2), "=r"(r3) : "r"(addr));
}

__device__ __forceinline__ unsigned packh2(__half a, __half b) {
    return (unsigned)__half_as_ushort(a) | ((unsigned)__half_as_ushort(b) << 16);
}
__device__ __forceinline__ void pack2(float x, float y, unsigned& hi, unsigned& lo) {
    __half hx = __float2half(x), hy = __float2half(y);
    __half lx = __float2half(x - __half2float(hx));
    __half ly = __float2half(y - __half2float(hy));
    hi = packh2(hx, hy);
    lo = packh2(lx, ly);
}

// ---------------- weight split conversion (vectorized) -----------------------
__global__ void k_split_w4(const float* __restrict__ src, __half* __restrict__ dst,
                           int total4, int K) {
    int idx = blockIdx.x * blockDim.x + threadIdx.x;
    if (idx >= total4) return;
    int i4 = idx * 4;
    int r = i4 / K;
    int k = i4 - r * K;
    float4 v = *(const float4*)&src[i4];
    __half h0 = __float2half(v.x), h1 = __float2half(v.y);
    __half h2 = __float2half(v.z), h3 = __float2half(v.w);
    __half l0 = __float2half(v.x - __half2float(h0));
    __half l1 = __float2half(v.y - __half2float(h1));
    __half l2 = __float2half(v.z - __half2float(h2));
    __half l3 = __float2half(v.w - __half2float(h3));
    size_t off = (size_t)r*2*K + k;
    uint2 uh; uh.x = packh2(h0,h1); uh.y = packh2(h2,h3);
    uint2 ul; ul.x = packh2(l0,l1); ul.y = packh2(l2,l3);
    *(uint2*)&dst[off]     = uh;
    *(uint2*)&dst[off + K] = ul;
}

__global__ void k_split_qkv_w4(const float* __restrict__ wq,
                               const float* __restrict__ wkv,
                               __half* __restrict__ dst) {
    int idx = blockIdx.x * blockDim.x + threadIdx.x;
    if (idx >= LLAYERS*3*CC*CC/4) return;
    int i4  = idx * 4;
    int l   = i4 / (3*CC*CC);
    int rem = i4 - l*(3*CC*CC);
    int row = rem >> 10;
    int k   = rem & 1023;
    float4 v = (row < CC)
        ? *(const float4*)&wq [((size_t)l*CC   + row)      * CC + k]
        : *(const float4*)&wkv[((size_t)l*2*CC + (row-CC)) * CC + k];
    __half h0 = __float2half(v.x), h1 = __float2half(v.y);
    __half h2 = __float2half(v.z), h3 = __float2half(v.w);
    __half l0 = __float2half(v.x - __half2float(h0));
    __half l1 = __float2half(v.y - __half2float(h1));
    __half l2 = __float2half(v.z - __half2float(h2));
    __half l3 = __float2half(v.w - __half2float(h3));
    __half* d = dst + ((size_t)l*3*CC + row)*2*CC;
    uint2 uh; uh.x = packh2(h0,h1); uh.y = packh2(h2,h3);
    uint2 ul; ul.x = packh2(l0,l1); ul.y = packh2(l2,l3);
    *(uint2*)&d[k]      = uh;
    *(uint2*)&d[CC + k] = ul;
}

// ---------------- input projection: h = x @ w_in^T  (K=9) --------------------
__global__ void k_input_proj(const float* __restrict__ x,
                             const float* __restrict__ w,
                             float* __restrict__ h) {
    int idx = blockIdx.x * blockDim.x + threadIdx.x;
    if (idx >= MM*CC) return;
    int m = idx >> 10;
    int c = idx & 1023;
    const float* xr = x + m*9;
    const float* wr = w + c*9;
    float s = 0.f;
    #pragma unroll
    for (int f = 0; f < 9; ++f) s += xr[f] * wr[f];
    h[idx] = s;
}

// ---------------- RMSNorm -> split fp16 hi/lo (vectorized) -------------------
__global__ void k_rms_h(const float* __restrict__ in,
                        __half* __restrict__ out2,     // [M][2C]
                        const float* __restrict__ g) {
    int m = blockIdx.x;
    int c4 = threadIdx.x * 4;
    float4 v = *(const float4*)&in[(size_t)m*CC + c4];
    float s = v.x*v.x + v.y*v.y + v.z*v.z + v.w*v.w;
    __shared__ float red[256];
    red[threadIdx.x] = s;
    __syncthreads();
    #pragma unroll
    for (int off = 128; off > 0; off >>= 1) {
        if (threadIdx.x < off) red[threadIdx.x] += red[threadIdx.x + off];
        __syncthreads();
    }
    float inv = rsqrtf(red[0] * (1.0f/CC) + 1e-5f);
    float4 gv = *(const float4*)&g[c4];
    float o0 = v.x*inv*gv.x, o1 = v.y*inv*gv.y;
    float o2 = v.z*inv*gv.z, o3 = v.w*inv*gv.w;
    unsigned h01, l01, h23, l23;
    pack2(o0, o1, h01, l01);
    pack2(o2, o3, h23, l23);
    uint2 uh; uh.x = h01; uh.y = h23;
    uint2 ul; ul.x = l01; ul.y = l23;
    *(uint2*)&out2[(size_t)m*2*CC + c4]      = uh;
    *(uint2*)&out2[(size_t)m*2*CC + CC + c4] = ul;
}

// ---------------- 3-stage pipelined ldmatrix fp16 tensor-core GEMM -----------
// C[M,N] (+)= A[M,K]*W[N,K]^T, single K pass.
// TERMS=3: Ahi*Whi + Alo*Whi + Ahi*Wlo.  TERMS=2: Ahi*Whi + Alo*Whi (Wlo unused,
// not even loaded).
// BM=BN=128, BK=32, 256 threads (8 warps, 4m x 2n, 32x64 warp tile).
// EPI: 0 = store fp32, 1 = add into fp32, 2 = silu(aux)*acc -> hi/lo fp16 out2.
#define GSTG 20480            // halves per stage (512 rows * 40)
#define GSMEM (3*GSTG*2)      // bytes = 122880
template<int EPI, int TERMS>
__global__ void __launch_bounds__(256, 1)
k_hgemm(const __half* __restrict__ A,
        const __half* __restrict__ W,
        float* __restrict__ C,
        const float* __restrict__ aux,
        __half* __restrict__ out2,
        int N, int K) {
    extern __shared__ __half sh[];
    int tid  = threadIdx.x;
    int wid  = tid >> 5, lane = tid & 31;
    int wm   = wid & 3,  wn   = wid >> 2;
    int g    = lane >> 2, t   = lane & 3;
    int m0   = blockIdx.y * 128, n0 = blockIdx.x * 128;
    int ld   = 2 * K;
    const int IT = K / 32;

    unsigned sb = (unsigned)__cvta_generic_to_shared(sh);
    unsigned aOff = (lane & 15)*80 + (lane >> 4)*16;
    unsigned bOff = ((lane & 7) + ((lane >> 4) << 3))*80 + ((lane >> 3) & 1)*16;

    float acc[2][8][4];
    #pragma unroll
    for (int mi = 0; mi < 2; ++mi)
        #pragma unroll
        for (int ni = 0; ni < 8; ++ni)
            #pragma unroll
            for (int q = 0; q < 4; ++q) acc[mi][ni][q] = 0.f;

    auto load_stage = [&](int st, int k0) {
        __half* base = sh + st*GSTG;
        const int NI = (TERMS == 3) ? 8 : 6;   // skip Wlo rows when 2-term
        #pragma unroll
        for (int i = 0; i < NI; ++i) {
            int c   = tid + i*256;
            int row = c >> 2;
            int kc  = (c & 3) * 8;
            const __half* src;
            if      (row < 128) src = A + (size_t)(m0 + row      )*ld + k0 + kc;
            else if (row < 256) src = A + (size_t)(m0 + row - 128)*ld + K + k0 + kc;
            else if (row < 384) src = W + (size_t)(n0 + row - 256)*ld + k0 + kc;
            else                src = W + (size_t)(n0 + row - 384)*ld + K + k0 + kc;
            cp16(base + row*40 + kc, src);
        }
    };

    auto compute_stage = [&](int st) {
        unsigned base = sb + st*(GSTG*2);
        unsigned aHb = base + (wm*32)*80 + aOff;
        unsigned aLb = aHb + 128*80;
        unsigned bHb = base + 256*80 + (wn*64)*80 + bOff;
        unsigned bLb = bHb + 128*80;
        #pragma unroll
        for (int kk = 0; kk < 32; kk += 16) {
            unsigned aH[2][4], aL[2][4], bh[8][2], bl[8][2];
            #pragma unroll
            for (int mi = 0; mi < 2; ++mi) {
                ldsm4(aHb + mi*16*80 + kk*2, aH[mi][0], aH[mi][1], aH[mi][2], aH[mi][3]);
                ldsm4(aLb + mi*16*80 + kk*2, aL[mi][0], aL[mi][1], aL[mi][2], aL[mi][3]);
            }
            #pragma unroll
            for (int nj = 0; nj < 4; ++nj) {
                ldsm4(bHb + nj*16*80 + kk*2,
                      bh[2*nj][0], bh[2*nj][1], bh[2*nj+1][0], bh[2*nj+1][1]);
                if (TERMS == 3)
                    ldsm4(bLb + nj*16*80 + kk*2,
                          bl[2*nj][0], bl[2*nj][1], bl[2*nj+1][0], bl[2*nj+1][1]);
            }
            #pragma unroll
            for (int ni = 0; ni < 8; ++ni)
                #pragma unroll
                for (int mi = 0; mi < 2; ++mi) {
                    mma16816(acc[mi][ni], aH[mi], bh[ni]);
                    mma16816(acc[mi][ni], aL[mi], bh[ni]);
                    if (TERMS == 3)
                        mma16816(acc[mi][ni], aH[mi], bl[ni]);
                }
        }
    };

    load_stage(0, 0);  CP_COMMIT();
    load_stage(1, 32); CP_COMMIT();
    for (int it = 0; it < IT; ++it) {
        CP_WAIT(1);
        __syncthreads();
        if (it + 2 < IT) load_stage((it+2)%3, (it+2)*32);
        CP_COMMIT();
        compute_stage(it % 3);
    }

    #pragma unroll
    for (int mi = 0; mi < 2; ++mi)
        #pragma unroll
        for (int ni = 0; ni < 8; ++ni) {
            int row = m0 + wm*32 + mi*16 + g;
            int col = n0 + wn*64 + ni*8 + 2*t;
            if (EPI == 0) {
                *(float2*)&C[(size_t)row*N + col] =
                    make_float2(acc[mi][ni][0], acc[mi][ni][1]);
                *(float2*)&C[(size_t)(row + 8)*N + col] =
                    make_float2(acc[mi][ni][2], acc[mi][ni][3]);
            } else if (EPI == 1) {
                float2* p0 = (float2*)&C[(size_t)row*N + col];
                float2* p1 = (float2*)&C[(size_t)(row + 8)*N + col];
                float2 v0 = *p0, v1 = *p1;
                v0.x += acc[mi][ni][0]; v0.y += acc[mi][ni][1];
                v1.x += acc[mi][ni][2]; v1.y += acc[mi][ni][3];
                *p0 = v0; *p1 = v1;
            } else {
                float2 a0v = *(const float2*)&aux[(size_t)row*N + col];
                float2 a1v = *(const float2*)&aux[(size_t)(row+8)*N + col];
                float v0 = a0v.x / (1.f + __expf(-a0v.x)) * acc[mi][ni][0];
                float v1 = a0v.y / (1.f + __expf(-a0v.y)) * acc[mi][ni][1];
                float v2 = a1v.x / (1.f + __expf(-a1v.x)) * acc[mi][ni][2];
                float v3 = a1v.y / (1.f + __expf(-a1v.y)) * acc[mi][ni][3];
                unsigned h01, l01, h23, l23;
                pack2(v0, v1, h01, l01);
                pack2(v2, v3, h23, l23);
                *(unsigned*)&out2[(size_t)row*2*N + col]          = h01;
                *(unsigned*)&out2[(size_t)row*2*N + N + col]      = l01;
                *(unsigned*)&out2[(size_t)(row+8)*2*N + col]      = h23;
                *(unsigned*)&out2[(size_t)(row+8)*2*N + N + col]  = l23;
            }
        }
}

// ---------------- RoPE + convert (tile-based, coalesced V^T, hi-only K/V) ----
// grid (TT/64, NH, B), 256 threads. Each CTA: 64 tokens x 64 dims of one head.
#define VP 66   // smem pitch (halves)
__global__ void k_rope_cvt2(const float* __restrict__ qkv,
                            __half* __restrict__ qh, __half* __restrict__ ql,
                            __half* __restrict__ kh,
                            __half* __restrict__ vth) {
    __shared__ __half vsh[64*VP];
    int tid = threadIdx.x;
    int qt = blockIdx.x, head = blockIdx.y, b = blockIdx.z;
    int t0 = qt * 64;

    #pragma unroll
    for (int it = 0; it < 8; ++it) {
        int e = tid + it*256;          // 0..2047 pairs
        int r = e >> 5;                // token row 0..63
        int i = e & 31;                // pair index
        int t = t0 + r;
        int m = b*TT + t;
        float invf = __powf(10000.0f, -(2.0f * i) / 64.0f);
        float ang  = (float)t * invf;
        float c, s;
        __sincosf(ang, &s, &c);

        size_t base = (size_t)m*(3*CC) + head*64 + i;
        size_t qo = (size_t)m*CC + head*64 + i;
        {
            float x1 = qkv[base], x2 = qkv[base+32];
            float r1 = (x1*c - x2*s) * 0.125f;
            float r2 = (x2*c + x1*s) * 0.125f;
            __half h1 = __float2half(r1), h2 = __float2half(r2);
            qh[qo]    = h1; ql[qo]    = __float2half(r1 - __half2float(h1));
            qh[qo+32] = h2; ql[qo+32] = __float2half(r2 - __half2float(h2));
        }
        {
            float x1 = qkv[base+CC], x2 = qkv[base+CC+32];
            kh[qo]    = __float2half(x1*c - x2*s);
            kh[qo+32] = __float2half(x2*c + x1*s);
        }
        {
            vsh[i*VP + r]      = __float2half(qkv[base+2*CC]);
            vsh[(i+32)*VP + r] = __float2half(qkv[base+2*CC+32]);
        }
    }
    __syncthreads();

    int d = tid >> 2;
    int rs = (tid & 3) * 16;
    size_t obase = ((size_t)(b*NHH + head)*DHH + d) * TT + t0 + rs;
    unsigned wh[8];
    #pragma unroll
    for (int j = 0; j < 8; ++j)
        wh[j] = packh2(vsh[d*VP + rs + 2*j], vsh[d*VP + rs + 2*j + 1]);
    uint4 o0, o1;
    o0.x = wh[0]; o0.y = wh[1]; o0.z = wh[2]; o0.w = wh[3];
    o1.x = wh[4]; o1.y = wh[5]; o1.z = wh[6]; o1.w = wh[7];
    *(uint4*)&vth[obase]     = o0;
    *(uint4*)&vth[obase + 8] = o1;
}

// ---------------- tensor-core flash attention (2-term, double-buffered) ------
// grid (T/64, NH, B), 128 threads; longest tiles scheduled first.
// QK = Qhi*Khi + Qlo*Khi;  PV = Phi*Vhi + Plo*Vhi  (Klo/Vlo dropped).
#define ASTG 9216               // halves per stage: 2 arrays * 64*72
#define ASMEM (2*ASTG*2)        // bytes = 36864
__global__ void k_attn_mma(const __half* __restrict__ qh, const __half* __restrict__ ql,
                           const __half* __restrict__ kh,
                           const __half* __restrict__ vth,
                           __half* __restrict__ y2) {
    extern __shared__ __half ash[];

    int tid = threadIdx.x, wid = tid >> 5, lane = tid & 31;
    int g = lane >> 2, t = lane & 3;
    int qt = (TT/64 - 1) - blockIdx.x;         // longest-first
    int head = blockIdx.y, b = blockIdx.z;

    auto load_tile = [&](int st, int kt) {
        __half* Kh = ash + st*ASTG;
        __half* Vh = Kh + 4608;
        #pragma unroll
        for (int i = 0; i < 4; ++i) {
            int cid = tid + i*128;
            int row = cid >> 3, ch = (cid & 7) * 8;
            size_t ksrc = (size_t)(b*TT + kt*64 + row)*CC + head*64 + ch;
            cp16(&Kh[row*72 + ch], kh + ksrc);
            size_t vsrc = ((size_t)(b*NHH + head)*DHH + row)*TT + kt*64 + ch;
            cp16(&Vh[row*72 + ch], vth + vsrc);
        }
    };

    unsigned aQh[4][4], aQl[4][4];
    {
        size_t r0 = (size_t)(b*TT + qt*64 + wid*16 + g) * CC + head*64;
        size_t r1 = r0 + 8*CC;
        #pragma unroll
        for (int ks = 0; ks < 4; ++ks) {
            int c0 = ks*16 + 2*t, c1 = c0 + 8;
            aQh[ks][0] = *(const unsigned*)&qh[r0 + c0];
            aQh[ks][1] = *(const unsigned*)&qh[r1 + c0];
            aQh[ks][2] = *(const unsigned*)&qh[r0 + c1];
            aQh[ks][3] = *(const unsigned*)&qh[r1 + c1];
            aQl[ks][0] = *(const unsigned*)&ql[r0 + c0];
            aQl[ks][1] = *(const unsigned*)&ql[r1 + c0];
            aQl[ks][2] = *(const unsigned*)&ql[r0 + c1];
            aQl[ks][3] = *(const unsigned*)&ql[r1 + c1];
        }
    }

    float O[8][4];
    #pragma unroll
    for (int n = 0; n < 8; ++n)
        #pragma unroll
        for (int q = 0; q < 4; ++q) O[n][q] = 0.f;
    float m0 = -INFINITY, m1 = -INFINITY, l0 = 0.f, l1 = 0.f;

    int st = 0;
    load_tile(0, 0);
    CP_COMMIT();

    for (int kt = 0; kt <= qt; ++kt) {
        if (kt + 1 <= qt) {
            load_tile(st ^ 1, kt + 1);
            CP_COMMIT();
            CP_WAIT(1);
        } else {
            CP_WAIT(0);
        }
        __syncthreads();

        __half* Kh = ash + st*ASTG;
        __half* Vh = Kh + 4608;

        float S[8][4];
        #pragma unroll
        for (int n = 0; n < 8; ++n) {
            S[n][0] = S[n][1] = S[n][2] = S[n][3] = 0.f;
            #pragma unroll
            for (int ks = 0; ks < 4; ++ks) {
                unsigned bh[2];
                bh[0] = *(const unsigned*)&Kh[(n*8+g)*72 + ks*16 + 2*t];
                bh[1] = *(const unsigned*)&Kh[(n*8+g)*72 + ks*16 + 2*t + 8];
                mma16816(S[n], aQh[ks], bh);
                mma16816(S[n], aQl[ks], bh);
            }
        }

        if (kt == qt) {
            int r0 = wid*16 + g, r1 = r0 + 8;
            #pragma unroll
            for (int n = 0; n < 8; ++n) {
                int c0 = n*8 + 2*t, c1 = c0 + 1;
                if (c0 > r0) S[n][0] = -INFINITY;
                if (c1 > r0) S[n][1] = -INFINITY;
                if (c0 > r1) S[n][2] = -INFINITY;
                if (c1 > r1) S[n][3] = -INFINITY;
            }
        }

        float mt0 = -INFINITY, mt1 = -INFINITY;
        #pragma unroll
        for (int n = 0; n < 8; ++n) {
            mt0 = fmaxf(mt0, fmaxf(S[n][0], S[n][1]));
            mt1 = fmaxf(mt1, fmaxf(S[n][2], S[n][3]));
        }
        mt0 = fmaxf(mt0, __shfl_xor_sync(0xffffffffu, mt0, 1));
        mt0 = fmaxf(mt0, __shfl_xor_sync(0xffffffffu, mt0, 2));
        mt1 = fmaxf(mt1, __shfl_xor_sync(0xffffffffu, mt1, 1));
        mt1 = fmaxf(mt1, __shfl_xor_sync(0xffffffffu, mt1, 2));
        float mn0 = fmaxf(m0, mt0), mn1 = fmaxf(m1, mt1);
        float a0 = __expf(m0 - mn0), a1 = __expf(m1 - mn1);
        float ls0 = 0.f, ls1 = 0.f;
        #pragma unroll
        for (int n = 0; n < 8; ++n) {
            S[n][0] = __expf(S[n][0] - mn0);
            S[n][1] = __expf(S[n][1] - mn0);
            S[n][2] = __expf(S[n][2] - mn1);
            S[n][3] = __expf(S[n][3] - mn1);
            ls0 += S[n][0] + S[n][1];
            ls1 += S[n][2] + S[n][3];
        }
        ls0 += __shfl_xor_sync(0xffffffffu, ls0, 1);
        ls0 += __shfl_xor_sync(0xffffffffu, ls0, 2);
        ls1 += __shfl_xor_sync(0xffffffffu, ls1, 1);
        ls1 += __shfl_xor_sync(0xffffffffu, ls1, 2);
        l0 = l0*a0 + ls0;  m0 = mn0;
        l1 = l1*a1 + ls1;  m1 = mn1;
        #pragma unroll
        for (int n = 0; n < 8; ++n) {
            O[n][0] *= a0; O[n][1] *= a0;
            O[n][2] *= a1; O[n][3] *= a1;
        }

        unsigned aPh[4][4], aPl[4][4];
        #pragma unroll
        for (int ks = 0; ks < 4; ++ks) {
            pack2(S[2*ks][0],   S[2*ks][1],   aPh[ks][0], aPl[ks][0]);
            pack2(S[2*ks][2],   S[2*ks][3],   aPh[ks][1], aPl[ks][1]);
            pack2(S[2*ks+1][0], S[2*ks+1][1], aPh[ks][2], aPl[ks][2]);
            pack2(S[2*ks+1][2], S[2*ks+1][3], aPh[ks][3], aPl[ks][3]);
        }

        #pragma unroll
        for (int n = 0; n < 8; ++n) {
            #pragma unroll
            for (int ks = 0; ks < 4; ++ks) {
                unsigned bh[2];
                bh[0] = *(const unsigned*)&Vh[(n*8+g)*72 + ks*16 + 2*t];
                bh[1] = *(const unsigned*)&Vh[(n*8+g)*72 + ks*16 + 2*t + 8];
                mma16816(O[n], aPh[ks], bh);
                mma16816(O[n], aPl[ks], bh);
            }
        }
        __syncthreads();
        st ^= 1;
    }

    float i0 = 1.f / l0, i1 = 1.f / l1;
    int row0 = b*TT + qt*64 + wid*16 + g;
    #pragma unroll
    for (int n = 0; n < 8; ++n) {
        int col = head*64 + n*8 + 2*t;
        float v0 = O[n][0]*i0, v1 = O[n][1]*i0;
        float v2 = O[n][2]*i1, v3 = O[n][3]*i1;
        unsigned h01, l01, h23, l23;
        pack2(v0, v1, h01, l01);
        pack2(v2, v3, h23, l23);
        *(unsigned*)&y2[(size_t)row0*2*CC + col]            = h01;
        *(unsigned*)&y2[(size_t)row0*2*CC + CC + col]       = l01;
        *(unsigned*)&y2[(size_t)(row0+8)*2*CC + col]        = h23;
        *(unsigned*)&y2[(size_t)(row0+8)*2*CC + CC + col]   = l23;
    }
}

// ---------------- final RMSNorm into d_out (vectorized) ----------------------
__global__ void k_rms_out4(const float* __restrict__ in,
                           float* __restrict__ out,
                           const float* __restrict__ g) {
    int m = blockIdx.x;
    int c4 = threadIdx.x * 4;
    float4 v = *(const float4*)&in[(size_t)m*CC + c4];
    float s = v.x*v.x + v.y*v.y + v.z*v.z + v.w*v.w;
    __shared__ float red[256];
    red[threadIdx.x] = s;
    __syncthreads();
    #pragma unroll
    for (int off = 128; off > 0; off >>= 1) {
        if (threadIdx.x < off) red[threadIdx.x] += red[threadIdx.x + off];
        __syncthreads();
    }
    float inv = rsqrtf(red[0] * (1.0f/CC) + 1e-5f);
    float4 gv = *(const float4*)&g[c4];
    float4 o;
    o.x = v.x*inv*gv.x; o.y = v.y*inv*gv.y;
    o.z = v.z*inv*gv.z; o.w = v.w*inv*gv.w;
    *(float4*)&out[(size_t)m*CC + c4] = o;
}

// ---------------- orchestration ----------------------------------------------
extern "C" void kernel_launch(void* const* d_in, const int* in_sizes, int n_in,
                              void* d_out, int out_size) {
    const float* x    = (const float*)d_in[0];
    const float* w_in = (const float*)d_in[1];
    const float* wq   = (const float*)d_in[2];
    const float* wkv  = (const float*)d_in[3];
    const float* wo   = (const float*)d_in[4];
    const float* w1   = (const float*)d_in[5];
    const float* w2   = (const float*)d_in[6];
    const float* w3   = (const float*)d_in[7];
    const float* g1   = (const float*)d_in[8];
    const float* g2   = (const float*)d_in[9];
    const float* gf   = (const float*)d_in[10];
    float* out = (float*)d_out;

    float *h, *qkvb, *u1;
    __half *a2, *y2, *u12, *wqkv2, *wo2, *w12, *w22, *w32;
    __half *qhp, *qlp, *khp, *vthp;
    cudaGetSymbolAddress((void**)&h,    g_h);
    cudaGetSymbolAddress((void**)&a2,   g_a2);
    cudaGetSymbolAddress((void**)&qkvb, g_qkv);
    cudaGetSymbolAddress((void**)&qhp,  g_qh);
    cudaGetSymbolAddress((void**)&qlp,  g_ql);
    cudaGetSymbolAddress((void**)&khp,  g_kh);
    cudaGetSymbolAddress((void**)&vthp, g_vth);
    cudaGetSymbolAddress((void**)&y2,   g_y2);
    cudaGetSymbolAddress((void**)&u1,   g_u1);
    cudaGetSymbolAddress((void**)&u12,  g_u12);
    cudaGetSymbolAddress((void**)&wqkv2,g_wqkv2);
    cudaGetSymbolAddress((void**)&wo2,  g_wo2);
    cudaGetSymbolAddress((void**)&w12,  g_w12);
    cudaGetSymbolAddress((void**)&w22,  g_w22);
    cudaGetSymbolAddress((void**)&w32,  g_w32);

    cudaFuncSetAttribute(k_hgemm<0,3>,
                         cudaFuncAttributeMaxDynamicSharedMemorySize, GSMEM);
    cudaFuncSetAttribute(k_hgemm<0,2>,
                         cudaFuncAttributeMaxDynamicSharedMemorySize, GSMEM);
    cudaFuncSetAttribute(k_hgemm<1,3>,
                         cudaFuncAttributeMaxDynamicSharedMemorySize, GSMEM);
    cudaFuncSetAttribute(k_hgemm<2,3>,
                         cudaFuncAttributeMaxDynamicSharedMemorySize, GSMEM);
    cudaFuncSetAttribute(k_attn_mma,
                         cudaFuncAttributeMaxDynamicSharedMemorySize, ASMEM);

    // weight splits (vectorized)
    {
        int n;
        n = LLAYERS*3*CC*CC/4;
        k_split_qkv_w4<<<(n+255)/256, 256>>>(wq, wkv, wqkv2);
        n = LLAYERS*CC*CC;
        k_split_w4<<<(n/4+255)/256, 256>>>(wo, wo2, n/4, CC);
        n = LLAYERS*HFF_*CC;
        k_split_w4<<<(n/4+255)/256, 256>>>(w1, w12, n/4, CC);
        k_split_w4<<<(n/4+255)/256, 256>>>(w2, w22, n/4, CC);
        n = LLAYERS*CC*HFF_;
        k_split_w4<<<(n/4+255)/256, 256>>>(w3, w32, n/4, HFF_);
    }

    k_input_proj<<<MM*CC/256, 256>>>(x, w_in, h);

    for (int l = 0; l < LLAYERS; ++l) {
        const __half* wqkv_l = wqkv2 + (size_t)l*3*CC*2*CC;
        const __half* wo_l   = wo2   + (size_t)l*CC*2*CC;
        const __half* w1_l   = w12   + (size_t)l*HFF_*2*CC;
        const __half* w2_l   = w22   + (size_t)l*HFF_*2*CC;
        const __half* w3_l   = w32   + (size_t)l*CC*2*HFF_;

        // --- attention block ---
        k_rms_h<<<MM, 256>>>(h, a2, g1 + l*CC);
        // q projection: full 3-term (ql is consumed by attention)
        k_hgemm<0,3><<<dim3(8,16), 256, GSMEM>>>(a2, wqkv_l, qkvb, nullptr, nullptr,
                                                 3*CC, CC);
        // k,v projection: 2-term (consumed fp16-hi only; error under rounding)
        k_hgemm<0,2><<<dim3(16,16), 256, GSMEM>>>(a2, wqkv_l + (size_t)CC*2*CC,
                                                  qkvb + CC, nullptr, nullptr,
                                                  3*CC, CC);
        k_rope_cvt2<<<dim3(TT/64, NHH, BB), 256>>>(qkvb, qhp, qlp, khp, vthp);
        k_attn_mma<<<dim3(TT/64, NHH, BB), 128, ASMEM>>>(qhp, qlp, khp, vthp, y2);
        k_hgemm<1,3><<<dim3(8,16), 256, GSMEM>>>(y2, wo_l, h, nullptr, nullptr,
                                                 CC, CC);

        // --- MLP block ---
        k_rms_h<<<MM, 256>>>(h, a2, g2 + l*CC);
        k_hgemm<0,3><<<dim3(22,16), 256, GSMEM>>>(a2, w1_l, u1, nullptr, nullptr,
                                                  HFF_, CC);
        k_hgemm<2,3><<<dim3(22,16), 256, GSMEM>>>(a2, w2_l, nullptr, u1, u12,
                                                  HFF_, CC);
        k_hgemm<1,3><<<dim3(8,16), 256, GSMEM>>>(u12, w3_l, h, nullptr, nullptr,
                                                 CC, HFF_);
    }

    k_rms_out4<<<MM, 256>>>(h, out, gf);
}